// round 16
// baseline (speedup 1.0000x reference)
#include <cuda_runtime.h>
#include <cuda_fp16.h>
#include <stdint.h>
#include <math.h>

#define BATCH 16
#define C_IN  256
#define W_DIM 64
#define HW    4096
#define HWP   1024
#define CK    32
#define CH    128
#define OC_TOT 192

#define LOG2E 1.44269504088896340736f

// Scratch. All attention operands fp16; proj weights fp16 (11-bit mantissa = tf32).
__device__ __half d_f16[(size_t)BATCH * HW * CK];     // [b][q][c]  f*log2e
__device__ __half d_g16[(size_t)BATCH * HWP * CK];    // [b][l][c]
__device__ __half d_h16[(size_t)BATCH * CH * HWP];    // [b][c][l]
__device__ __half d_wcat16[OC_TOT * C_IN];            // [oc][256] (f*log2e, g, h)
__device__ __half d_wvt16[C_IN * CH];                 // [oc][c]

// ---------------------------------------------------------------------------
__device__ __forceinline__ float ex2f(float x) {
    float y; asm("ex2.approx.ftz.f32 %0, %1;" : "=f"(y) : "f"(x)); return y;
}
__device__ __forceinline__ uint32_t h2pack(float lo, float hi) {
    uint32_t r; asm("cvt.rn.f16x2.f32 %0, %1, %2;" : "=r"(r) : "f"(hi), "f"(lo)); return r;
}
__device__ __forceinline__ uint32_t ex2h2(uint32_t x) {
    uint32_t y; asm("ex2.approx.f16x2 %0, %1;" : "=r"(y) : "r"(x)); return y;
}

// fp16 mma m16n8k16
__device__ __forceinline__ void mma16h(float* d, const uint32_t* a, const uint32_t* b) {
    asm volatile(
        "mma.sync.aligned.m16n8k16.row.col.f32.f16.f16.f32 "
        "{%0,%1,%2,%3},{%4,%5,%6,%7},{%8,%9},{%0,%1,%2,%3};\n"
        : "+f"(d[0]), "+f"(d[1]), "+f"(d[2]), "+f"(d[3])
        : "r"(a[0]), "r"(a[1]), "r"(a[2]), "r"(a[3]), "r"(b[0]), "r"(b[1]));
}

__device__ __forceinline__ uint32_t s2u(const void* p) {
    return (uint32_t)__cvta_generic_to_shared(p);
}
__device__ __forceinline__ void cp16(void* dst, const void* src) {
    asm volatile("cp.async.cg.shared.global [%0], [%1], 16;\n" :: "r"(s2u(dst)), "l"(src));
}
__device__ __forceinline__ void cp_commit() { asm volatile("cp.async.commit_group;\n" ::); }
__device__ __forceinline__ void cp_wait_all() { asm volatile("cp.async.wait_group 0;\n" ::); }

// fp16 A fragment m16k16 via ldmatrix (k step = 8 words)
__device__ __forceinline__ void ldsmA(uint32_t* r, const uint32_t* base, int rs,
                                      int m_base, int k_base, int lane) {
    const uint32_t* p = base + (size_t)(m_base + (lane & 15)) * rs + k_base + ((lane >> 4) << 2);
    uint32_t addr = s2u(p);
    asm volatile("ldmatrix.sync.aligned.m8n8.x4.shared.b16 {%0,%1,%2,%3},[%4];"
                 : "=r"(r[0]), "=r"(r[1]), "=r"(r[2]), "=r"(r[3]) : "r"(addr));
}
// fp16 B fragments, two n8 tiles (k16)
__device__ __forceinline__ void ldsmB(uint32_t* r, const uint32_t* base, int rs,
                                      int n_base, int k_base, int lane) {
    int row = n_base + (lane & 7) + (((lane >> 4) & 1) << 3);
    int col = k_base + (((lane >> 3) & 1) << 2);
    const uint32_t* p = base + (size_t)row * rs + col;
    uint32_t addr = s2u(p);
    asm volatile("ldmatrix.sync.aligned.m8n8.x4.shared.b16 {%0,%1,%2,%3},[%4];"
                 : "=r"(r[0]), "=r"(r[1]), "=r"(r[2]), "=r"(r[3]) : "r"(addr));
}

#define AP20 20    // proj A / attn g fp16 pitch (80B rows -> 8 distinct 16B groups)
#define PB   132   // proj B [k][n] fp32 pitch: 264 mod 32 = 8 -> pack-LDS conflict-free
#define HS68 68    // attn h [c][128 l] fp16 pitch (272B = 16 mod 128)
#define PP68 68    // attn P [q][128 l] fp16 pitch
#define OP68 68    // o_s / wv_s [*][128 c] fp16 pitch

#define LC 128
#define NCHUNK 8

// ---------------------------------------------------------------------------
// Kernel 0: prep weights -> fp16 (wf scaled by log2e)
// ---------------------------------------------------------------------------
__global__ __launch_bounds__(256)
void prep_weights(const float* __restrict__ wf, const float* __restrict__ wg,
                  const float* __restrict__ wh, const float* __restrict__ wv)
{
    int i = blockIdx.x * 256 + threadIdx.x;
    if (i < OC_TOT * C_IN) {
        int oc = i >> 8, k = i & 255;
        float v;
        if (oc < 32)       v = wf[oc * C_IN + k] * LOG2E;
        else if (oc < 64)  v = wg[(oc - 32) * C_IN + k];
        else               v = wh[(oc - 64) * C_IN + k];
        d_wcat16[i] = __float2half(v);
    }
    int j = i - OC_TOT * C_IN;
    if (j >= 0 && j < C_IN * CH) d_wvt16[j] = __float2half(wv[j]);
}

// ---------------------------------------------------------------------------
// Kernel 1: projection GEMM (fp16 mma, B packed from fp32 in regs)
//           + bias + fused 2x2 maxpool; fp16 outputs.
// ---------------------------------------------------------------------------
__global__ __launch_bounds__(256)
void proj_gemm(const float* __restrict__ x,
               const float* __restrict__ bf, const float* __restrict__ bg,
               const float* __restrict__ bh)
{
    extern __shared__ uint32_t smp[];
    uint32_t* As = smp;                       // 2 x [64 m][AP20] fp16   2560 w
    uint32_t* Bs = As + 2 * 64 * AP20;        // 2 x [32 k][PB] fp32     8448 w

    const int b  = blockIdx.z;
    const int n0 = blockIdx.x * 128;
    const int m0 = blockIdx.y * 64;
    const float* xb = x + (size_t)b * C_IN * HW;

    const int t = threadIdx.x, lane = t & 31, wid = t >> 5;
    const int wm = wid & 1, wn = wid >> 1;

    auto issue_chunk = [&](int k0, int buf) {
        uint32_t* ad = As + buf * 64 * AP20;
        uint32_t* bd = Bs + buf * 32 * PB;
        // A: [64 m][32 k] fp16, 256 cp16 (1/thread)
        {
            int m = t >> 2, seg = t & 3;
            cp16(&ad[m * AP20 + seg * 4], d_wcat16 + (size_t)(m0 + m) * C_IN + k0 + seg * 8);
        }
        // B: [32 k][128 n] fp32 native, cp16 (4/thread)
        #pragma unroll
        for (int ii = 0; ii < 4; ii++) {
            int i = t + ii * 256;
            int k = i >> 5, n4 = (i & 31) * 4;
            cp16(&bd[k * PB + n4], xb + (size_t)(k0 + k) * HW + n0 + n4);
        }
        cp_commit();
    };

    issue_chunk(0, 0);

    float acc[2][4][4] = {};

    for (int ic = 0; ic < 8; ic++) {
        cp_wait_all();
        __syncthreads();
        if (ic + 1 < 8) issue_chunk((ic + 1) * 32, (ic + 1) & 1);

        const uint32_t* abuf = As + (ic & 1) * 64 * AP20;
        const float* bbuf = reinterpret_cast<const float*>(Bs + (ic & 1) * 32 * PB);

        #pragma unroll
        for (int kk = 0; kk < 2; kk++) {
            uint32_t a0[4], a1[4];
            ldsmA(a0, abuf, AP20, wm * 32,      kk * 8, lane);
            ldsmA(a1, abuf, AP20, wm * 32 + 16, kk * 8, lane);
            // build fp16 B frags from fp32 smem (conflict-free: banks 8*(lane&3)+(lane>>2))
            int kb = kk * 16 + 2 * (lane & 3);
            int nb = wn * 32 + (lane >> 2);
            uint32_t bfr[4][2];
            #pragma unroll
            for (int ntp = 0; ntp < 4; ntp++) {
                int n = nb + ntp * 8;
                bfr[ntp][0] = h2pack(bbuf[(size_t)kb * PB + n],       bbuf[(size_t)(kb + 1) * PB + n]);
                bfr[ntp][1] = h2pack(bbuf[(size_t)(kb + 8) * PB + n], bbuf[(size_t)(kb + 9) * PB + n]);
            }
            mma16h(acc[0][0], a0, bfr[0]); mma16h(acc[0][1], a0, bfr[1]);
            mma16h(acc[0][2], a0, bfr[2]); mma16h(acc[0][3], a0, bfr[3]);
            mma16h(acc[1][0], a1, bfr[0]); mma16h(acc[1][1], a1, bfr[1]);
            mma16h(acc[1][2], a1, bfr[2]); mma16h(acc[1][3], a1, bfr[3]);
        }
    }
    __syncthreads();

    // epilogue: f staged to As region fp16 [q][c]; g/h pooled via Bs region.
    __half* fsm = reinterpret_cast<__half*>(As);                  // [128 q][32 c]  2048 w
    float* psm  = reinterpret_cast<float*>(Bs);                   // [64][2][32]    4096 w

    #pragma unroll
    for (int mt = 0; mt < 2; mt++) {
        #pragma unroll
        for (int dr = 0; dr < 2; dr++) {
            int ocl = wm * 32 + mt * 16 + dr * 8 + (lane >> 2);
            int oc = m0 + ocl;
            #pragma unroll
            for (int nt = 0; nt < 4; nt++) {
                int nloc = wn * 32 + nt * 8 + 2 * (lane & 3);
                float v0 = acc[mt][nt][dr * 2 + 0];
                float v1 = acc[mt][nt][dr * 2 + 1];
                if (oc < 32) {
                    float bias = bf[oc] * LOG2E;
                    fsm[(size_t)nloc * 32 + ocl]       = __float2half(v0 + bias);
                    fsm[(size_t)(nloc + 1) * 32 + ocl] = __float2half(v1 + bias);
                } else {
                    int pr = nloc >> 6;
                    int pw = (nloc & 63) >> 1;
                    psm[ocl * 64 + pr * 32 + pw] = fmaxf(v0, v1);
                }
            }
        }
    }
    __syncthreads();

    int ph = n0 >> 7;
    for (int i = t; i < 64 * 32; i += 256) {
        int ocl = i >> 5, pw = i & 31;
        int oc = m0 + ocl;
        if (oc >= 32) {
            float v = fmaxf(psm[ocl * 64 + pw], psm[ocl * 64 + 32 + pw]);
            int l = ph * 32 + pw;
            if (oc < 64)
                d_g16[((size_t)b * HWP + l) * CK + (oc - 32)] = __float2half(v + bg[oc - 32]);
            else
                d_h16[((size_t)b * CH + (oc - 64)) * HWP + l] = __float2half(v + bh[oc - 64]);
        }
    }
    if (m0 == 0) {
        #pragma unroll
        for (int ii = 0; ii < 2; ii++) {
            int i = t + ii * 256;
            int q = i >> 2, seg = i & 3;
            *reinterpret_cast<uint4*>(d_f16 + ((size_t)b * HW + n0 + q) * CK + seg * 8) =
                *reinterpret_cast<const uint4*>(fsm + (size_t)q * 32 + seg * 8);
        }
    }
}

// ---------------------------------------------------------------------------
// Kernel 2: fp16 flash attention, l-chunks of 128, f16x2 exp, fused out conv.
// ---------------------------------------------------------------------------
__global__ __launch_bounds__(256, 2)
void attn_kernel(const float* __restrict__ x,
                 const float* __restrict__ bv,
                 const float* __restrict__ gamma_p,
                 float* __restrict__ out)
{
    extern __shared__ uint32_t sm[];
    uint32_t* g_s = sm;                          // 2 x [128 l][AP20]   5120 w
    uint32_t* h_s = g_s + 2 * 128 * AP20;        // 2 x [128 c][HS68]  17408 w
    uint32_t* p_u = h_s + 2 * 128 * HS68;        // [64 q][PP68] fp16   4352 w
    float* maxp     = reinterpret_cast<float*>(p_u + 64 * PP68);   // [4][64]
    float* row_part = maxp + 256;                                  // [4][64]
    // epilogue overlays:
    uint32_t* o_s  = sm;                         // [64 q][OP68]        4352 w
    uint32_t* wv_s = sm + 64 * OP68;             // 2 x [64 oc][OP68]   8704 w

    const int b  = blockIdx.y;
    const int q0 = blockIdx.x * 64;
    const int t = threadIdx.x, lane = t & 31, wid = t >> 5;
    const int wm = wid & 1, wn = wid >> 1;

    const __half* fb = d_f16 + (size_t)b * HW * CK;
    const __half* gb = d_g16 + (size_t)b * HWP * CK;
    const __half* hb = d_h16 + (size_t)b * CH * HWP;

    auto issue_chunk = [&](int lc, int buf) {
        uint32_t* gd = g_s + buf * 128 * AP20;
        uint32_t* hd = h_s + buf * 128 * HS68;
        // g: [128 l][32 c] fp16, 512 cp16 (2/thread)
        #pragma unroll
        for (int ii = 0; ii < 2; ii++) {
            int i = t + ii * 256;
            int l = i >> 2, cseg = i & 3;
            cp16(&gd[l * AP20 + cseg * 4], gb + (size_t)(lc + l) * CK + cseg * 8);
        }
        // h: [128 c][128 l] fp16, 2048 cp16 (8/thread)
        #pragma unroll
        for (int ii = 0; ii < 8; ii++) {
            int i = t + ii * 256;
            int c = i >> 4, lseg = i & 15;
            cp16(&hd[c * HS68 + lseg * 4], hb + (size_t)c * HWP + lc + lseg * 8);
        }
        cp_commit();
    };

    issue_chunk(0, 0);

    // f A-fragments (fp16 m16k16), constant across chunks
    uint32_t fa[2][2][4];
    {
        int r0 = q0 + wm * 32 + (lane >> 2);
        int c0 = 2 * (lane & 3);
        #pragma unroll
        for (int mt = 0; mt < 2; mt++)
            #pragma unroll
            for (int kk = 0; kk < 2; kk++)
                #pragma unroll
                for (int j = 0; j < 4; j++) {
                    int row = r0 + mt * 16 + 8 * (j & 1);
                    int col = kk * 16 + 8 * (j >> 1) + c0;
                    fa[mt][kk][j] = *reinterpret_cast<const uint32_t*>(fb + (size_t)row * CK + col);
                }
    }

    float acc[2][4][4] = {};
    float rsum[2][2] = {};
    float mrun[2][2] = {{-1e30f, -1e30f}, {-1e30f, -1e30f}};

    for (int ic = 0; ic < NCHUNK; ic++) {
        cp_wait_all();
        __syncthreads();
        if (ic + 1 < NCHUNK) issue_chunk((ic + 1) * LC, (ic + 1) & 1);

        const uint32_t* gbuf = g_s + (ic & 1) * 128 * AP20;
        const uint32_t* hbuf = h_s + (ic & 1) * 128 * HS68;

        // --- S' = (f*log2e) * g  (warp: 32q x 32l) ---
        float sacc[2][4][4] = {};
        #pragma unroll
        for (int kk = 0; kk < 2; kk++) {
            uint32_t b01[4], b23[4];
            ldsmB(b01, gbuf, AP20, wn * 32,      kk * 8, lane);
            ldsmB(b23, gbuf, AP20, wn * 32 + 16, kk * 8, lane);
            mma16h(sacc[0][0], fa[0][kk], b01); mma16h(sacc[0][1], fa[0][kk], b01 + 2);
            mma16h(sacc[0][2], fa[0][kk], b23); mma16h(sacc[0][3], fa[0][kk], b23 + 2);
            mma16h(sacc[1][0], fa[1][kk], b01); mma16h(sacc[1][1], fa[1][kk], b01 + 2);
            mma16h(sacc[1][2], fa[1][kk], b23); mma16h(sacc[1][3], fa[1][kk], b23 + 2);
        }

        // --- per-chunk row max (exact) ---
        float lmax[2][2];
        #pragma unroll
        for (int mt = 0; mt < 2; mt++) {
            lmax[mt][0] = fmaxf(fmaxf(fmaxf(sacc[mt][0][0], sacc[mt][0][1]),
                                      fmaxf(sacc[mt][1][0], sacc[mt][1][1])),
                                fmaxf(fmaxf(sacc[mt][2][0], sacc[mt][2][1]),
                                      fmaxf(sacc[mt][3][0], sacc[mt][3][1])));
            lmax[mt][1] = fmaxf(fmaxf(fmaxf(sacc[mt][0][2], sacc[mt][0][3]),
                                      fmaxf(sacc[mt][1][2], sacc[mt][1][3])),
                                fmaxf(fmaxf(sacc[mt][2][2], sacc[mt][2][3]),
                                      fmaxf(sacc[mt][3][2], sacc[mt][3][3])));
            #pragma unroll
            for (int hh = 0; hh < 2; hh++) {
                float v = lmax[mt][hh];
                v = fmaxf(v, __shfl_xor_sync(0xffffffffu, v, 1));
                v = fmaxf(v, __shfl_xor_sync(0xffffffffu, v, 2));
                lmax[mt][hh] = v;
            }
        }
        if ((lane & 3) == 0) {
            #pragma unroll
            for (int mt = 0; mt < 2; mt++) {
                int rb = wm * 32 + mt * 16 + (lane >> 2);
                maxp[wn * 64 + rb]     = lmax[mt][0];
                maxp[wn * 64 + rb + 8] = lmax[mt][1];
            }
        }
        __syncthreads();

        // --- rescale, exp2 (f16x2), store P (fp16) ---
        #pragma unroll
        for (int mt = 0; mt < 2; mt++) {
            int rb = wm * 32 + mt * 16 + (lane >> 2);
            float cm0 = fmaxf(fmaxf(maxp[rb],       maxp[64 + rb]),
                              fmaxf(maxp[128 + rb], maxp[192 + rb]));
            float cm1 = fmaxf(fmaxf(maxp[rb + 8],       maxp[64 + rb + 8]),
                              fmaxf(maxp[128 + rb + 8], maxp[192 + rb + 8]));
            float mn0 = fmaxf(mrun[mt][0], cm0);
            float mn1 = fmaxf(mrun[mt][1], cm1);
            float corr0 = ex2f(mrun[mt][0] - mn0);
            float corr1 = ex2f(mrun[mt][1] - mn1);
            mrun[mt][0] = mn0; mrun[mt][1] = mn1;
            float ls0 = 0.f, ls1 = 0.f;
            #pragma unroll
            for (int nt = 0; nt < 4; nt++) {
                int cl = wn * 32 + nt * 8 + 2 * (lane & 3);
                uint32_t p01 = ex2h2(h2pack(sacc[mt][nt][0] - mn0, sacc[mt][nt][1] - mn0));
                uint32_t p23 = ex2h2(h2pack(sacc[mt][nt][2] - mn1, sacc[mt][nt][3] - mn1));
                p_u[rb * PP68 + (cl >> 1)]       = p01;
                p_u[(rb + 8) * PP68 + (cl >> 1)] = p23;
                float2 f01 = __half22float2(*reinterpret_cast<__half2*>(&p01));
                float2 f23 = __half22float2(*reinterpret_cast<__half2*>(&p23));
                ls0 += f01.x + f01.y;
                ls1 += f23.x + f23.y;
            }
            rsum[mt][0] = rsum[mt][0] * corr0 + ls0;
            rsum[mt][1] = rsum[mt][1] * corr1 + ls1;
            #pragma unroll
            for (int nt = 0; nt < 4; nt++) {
                acc[mt][nt][0] *= corr0; acc[mt][nt][1] *= corr0;
                acc[mt][nt][2] *= corr1; acc[mt][nt][3] *= corr1;
            }
        }
        __syncthreads();

        // --- O += P * h^T  (k = 128 l -> 8 k16 steps) ---
        #pragma unroll
        for (int kk = 0; kk < 8; kk++) {
            uint32_t a0[4], a1[4], b01[4], b23[4];
            ldsmA(a0, p_u, PP68, wm * 32,      kk * 8, lane);
            ldsmA(a1, p_u, PP68, wm * 32 + 16, kk * 8, lane);
            ldsmB(b01, hbuf, HS68, wn * 32,      kk * 8, lane);
            ldsmB(b23, hbuf, HS68, wn * 32 + 16, kk * 8, lane);
            mma16h(acc[0][0], a0, b01); mma16h(acc[0][1], a0, b01 + 2);
            mma16h(acc[0][2], a0, b23); mma16h(acc[0][3], a0, b23 + 2);
            mma16h(acc[1][0], a1, b01); mma16h(acc[1][1], a1, b01 + 2);
            mma16h(acc[1][2], a1, b23); mma16h(acc[1][3], a1, b23 + 2);
        }
    }

    // final row-sum reduction
    #pragma unroll
    for (int mt = 0; mt < 2; mt++)
        #pragma unroll
        for (int hh = 0; hh < 2; hh++) {
            float s = rsum[mt][hh];
            s += __shfl_xor_sync(0xffffffffu, s, 1);
            s += __shfl_xor_sync(0xffffffffu, s, 2);
            rsum[mt][hh] = s;
        }
    if ((lane & 3) == 0) {
        #pragma unroll
        for (int mt = 0; mt < 2; mt++)
            #pragma unroll
            for (int hh = 0; hh < 2; hh++) {
                int rb = wm * 32 + mt * 16 + hh * 8 + (lane >> 2);
                row_part[wn * 64 + rb] = rsum[mt][hh];
            }
    }
    __syncthreads();

    auto issue_wv = [&](int mc, int buf) {
        uint32_t* ad = wv_s + buf * 64 * OP68;
        #pragma unroll
        for (int ii = 0; ii < 4; ii++) {
            int i = t + ii * 256;
            int m = i >> 4, cseg = i & 15;
            cp16(&ad[m * OP68 + cseg * 4], d_wvt16 + (size_t)(mc * 64 + m) * CH + cseg * 8);
        }
        cp_commit();
    };

    issue_wv(0, 0);

    // normalize O -> o_s [q][c] fp16
    #pragma unroll
    for (int mt = 0; mt < 2; mt++) {
        int rb = wm * 32 + mt * 16 + (lane >> 2);
        float d0 = row_part[rb]     + row_part[64 + rb]     + row_part[128 + rb]     + row_part[192 + rb];
        float d1 = row_part[rb + 8] + row_part[64 + rb + 8] + row_part[128 + rb + 8] + row_part[192 + rb + 8];
        float inv0 = 1.f / d0;
        float inv1 = 1.f / d1;
        #pragma unroll
        for (int nt = 0; nt < 4; nt++) {
            int cc = wn * 32 + nt * 8 + 2 * (lane & 3);
            o_s[rb * OP68 + (cc >> 1)] =
                h2pack(acc[mt][nt][0] * inv0, acc[mt][nt][1] * inv0);
            o_s[(rb + 8) * OP68 + (cc >> 1)] =
                h2pack(acc[mt][nt][2] * inv1, acc[mt][nt][3] * inv1);
        }
    }

    // out[oc, q] = gamma * (wv @ O^T + bv) + x, 4 oc-chunks of 64 (fp16 mma)
    const float gamma = *gamma_p;

    for (int mc = 0; mc < 4; mc++) {
        cp_wait_all();
        __syncthreads();
        if (mc + 1 < 4) issue_wv(mc + 1, (mc + 1) & 1);

        const uint32_t* abuf = wv_s + (mc & 1) * 64 * OP68;

        float oa[2][2][4] = {};
        #pragma unroll
        for (int kk = 0; kk < 8; kk++) {
            uint32_t a0[4], a1[4], bq[4];
            ldsmA(a0, abuf, OP68, wm * 32,      kk * 8, lane);
            ldsmA(a1, abuf, OP68, wm * 32 + 16, kk * 8, lane);
            ldsmB(bq, o_s, OP68, wn * 16, kk * 8, lane);
            mma16h(oa[0][0], a0, bq); mma16h(oa[0][1], a0, bq + 2);
            mma16h(oa[1][0], a1, bq); mma16h(oa[1][1], a1, bq + 2);
        }

        #pragma unroll
        for (int mt = 0; mt < 2; mt++) {
            #pragma unroll
            for (int dr = 0; dr < 2; dr++) {
                int oc = mc * 64 + wm * 32 + mt * 16 + dr * 8 + (lane >> 2);
                float bias = bv[oc];
                size_t rowoff = ((size_t)b * C_IN + oc) * HW + q0;
                #pragma unroll
                for (int nt = 0; nt < 2; nt++) {
                    int ql = wn * 16 + nt * 8 + 2 * (lane & 3);
                    float2 xv = *reinterpret_cast<const float2*>(x + rowoff + ql);
                    float2 v;
                    v.x = gamma * (oa[mt][nt][dr * 2 + 0] + bias) + xv.x;
                    v.y = gamma * (oa[mt][nt][dr * 2 + 1] + bias) + xv.y;
                    *reinterpret_cast<float2*>(out + rowoff + ql) = v;
                }
            }
        }
    }
}

// ---------------------------------------------------------------------------
extern "C" void kernel_launch(void* const* d_in, const int* in_sizes, int n_in,
                              void* d_out, int out_size)
{
    const float* x  = (const float*)d_in[0];
    const float* wf = (const float*)d_in[1];
    const float* bf = (const float*)d_in[2];
    const float* wg = (const float*)d_in[3];
    const float* bg = (const float*)d_in[4];
    const float* wh = (const float*)d_in[5];
    const float* bh = (const float*)d_in[6];
    const float* wv = (const float*)d_in[7];
    const float* bv = (const float*)d_in[8];
    const float* gamma = (const float*)d_in[9];
    float* out = (float*)d_out;

    const int proj_smem = (2 * 64 * AP20 + 2 * 32 * PB) * (int)sizeof(uint32_t);
    const int attn_smem =
        (2 * 128 * AP20 + 2 * 128 * HS68 + 64 * PP68 + 512) * (int)sizeof(uint32_t);

    cudaFuncSetAttribute(proj_gemm,   cudaFuncAttributeMaxDynamicSharedMemorySize, proj_smem);
    cudaFuncSetAttribute(attn_kernel, cudaFuncAttributeMaxDynamicSharedMemorySize, attn_smem);

    int prep_total = OC_TOT * C_IN + C_IN * CH;
    prep_weights<<<(prep_total + 255) / 256, 256>>>(wf, wg, wh, wv);

    dim3 g1(HW / 128, OC_TOT / 64, BATCH);
    proj_gemm<<<g1, 256, proj_smem>>>(x, bf, bg, bh);

    dim3 g3(HW / 64, BATCH);
    attn_kernel<<<g3, 256, attn_smem>>>(x, bv, gamma, out);
}

// round 17
// speedup vs baseline: 1.3799x; 1.3799x over previous
#include <cuda_runtime.h>
#include <cuda_fp16.h>
#include <stdint.h>
#include <math.h>

#define BATCH 16
#define C_IN  256
#define W_DIM 64
#define HW    4096
#define HWP   1024
#define CK    32
#define CH    128
#define OC_TOT 192

#define LOG2E 1.44269504088896340736f

// Scratch. All operands fp16 (11-bit mantissa = tf32 mantissa).
__device__ __half d_f16[(size_t)BATCH * HW * CK];     // [b][q][c]  f*log2e
__device__ __half d_g16[(size_t)BATCH * HWP * CK];    // [b][l][c]
__device__ __half d_h16[(size_t)BATCH * CH * HWP];    // [b][c][l]
__device__ __half d_wcat16[OC_TOT * C_IN];            // [oc][256] (f*log2e, g, h)
__device__ __half d_wvt16[C_IN * CH];                 // [oc][c]

// ---------------------------------------------------------------------------
__device__ __forceinline__ float ex2f(float x) {
    float y; asm("ex2.approx.ftz.f32 %0, %1;" : "=f"(y) : "f"(x)); return y;
}
__device__ __forceinline__ uint32_t h2pack(float lo, float hi) {
    uint32_t r; asm("cvt.rn.f16x2.f32 %0, %1, %2;" : "=r"(r) : "f"(hi), "f"(lo)); return r;
}
__device__ __forceinline__ uint32_t ex2h2(uint32_t x) {
    uint32_t y; asm("ex2.approx.f16x2 %0, %1;" : "=r"(y) : "r"(x)); return y;
}

// fp16 mma m16n8k16
__device__ __forceinline__ void mma16h(float* d, const uint32_t* a, const uint32_t* b) {
    asm volatile(
        "mma.sync.aligned.m16n8k16.row.col.f32.f16.f16.f32 "
        "{%0,%1,%2,%3},{%4,%5,%6,%7},{%8,%9},{%0,%1,%2,%3};\n"
        : "+f"(d[0]), "+f"(d[1]), "+f"(d[2]), "+f"(d[3])
        : "r"(a[0]), "r"(a[1]), "r"(a[2]), "r"(a[3]), "r"(b[0]), "r"(b[1]));
}

__device__ __forceinline__ uint32_t s2u(const void* p) {
    return (uint32_t)__cvta_generic_to_shared(p);
}
__device__ __forceinline__ void cp16(void* dst, const void* src) {
    asm volatile("cp.async.cg.shared.global [%0], [%1], 16;\n" :: "r"(s2u(dst)), "l"(src));
}
__device__ __forceinline__ void cp_commit() { asm volatile("cp.async.commit_group;\n" ::); }
__device__ __forceinline__ void cp_wait_all() { asm volatile("cp.async.wait_group 0;\n" ::); }

// fp16 A fragment m16k16 via ldmatrix (k step = 8 words)
__device__ __forceinline__ void ldsmA(uint32_t* r, const uint32_t* base, int rs,
                                      int m_base, int k_base, int lane) {
    const uint32_t* p = base + (size_t)(m_base + (lane & 15)) * rs + k_base + ((lane >> 4) << 2);
    uint32_t addr = s2u(p);
    asm volatile("ldmatrix.sync.aligned.m8n8.x4.shared.b16 {%0,%1,%2,%3},[%4];"
                 : "=r"(r[0]), "=r"(r[1]), "=r"(r[2]), "=r"(r[3]) : "r"(addr));
}
// fp16 B fragments, two n8 tiles (k16)
__device__ __forceinline__ void ldsmB(uint32_t* r, const uint32_t* base, int rs,
                                      int n_base, int k_base, int lane) {
    int row = n_base + (lane & 7) + (((lane >> 4) & 1) << 3);
    int col = k_base + (((lane >> 3) & 1) << 2);
    const uint32_t* p = base + (size_t)row * rs + col;
    uint32_t addr = s2u(p);
    asm volatile("ldmatrix.sync.aligned.m8n8.x4.shared.b16 {%0,%1,%2,%3},[%4];"
                 : "=r"(r[0]), "=r"(r[1]), "=r"(r[2]), "=r"(r[3]) : "r"(addr));
}

#define AP20 20    // fp16 [*][32] pitch (80B rows -> 8 distinct 16B groups)
#define PB   132   // proj B [k][n] fp32 pitch: 264 mod 32 = 8 -> pack-LDS conflict-free
#define GP20 20    // attn g [l][c] fp16 pitch
#define PP36 36    // attn P [q][64 l] fp16 pitch
#define HS36 36    // attn h [c][64 l] fp16 pitch
#define OP68 68    // o_s / wv_s [*][128 c] fp16 pitch (272B = 16 mod 128)

#define LC 64
#define NCHUNK 16

// ---------------------------------------------------------------------------
// Kernel 0: prep weights -> fp16 (wf scaled by log2e)
// ---------------------------------------------------------------------------
__global__ __launch_bounds__(256)
void prep_weights(const float* __restrict__ wf, const float* __restrict__ wg,
                  const float* __restrict__ wh, const float* __restrict__ wv)
{
    int i = blockIdx.x * 256 + threadIdx.x;
    if (i < OC_TOT * C_IN) {
        int oc = i >> 8, k = i & 255;
        float v;
        if (oc < 32)       v = wf[oc * C_IN + k] * LOG2E;
        else if (oc < 64)  v = wg[(oc - 32) * C_IN + k];
        else               v = wh[(oc - 64) * C_IN + k];
        d_wcat16[i] = __float2half(v);
    }
    int j = i - OC_TOT * C_IN;
    if (j >= 0 && j < C_IN * CH) d_wvt16[j] = __float2half(wv[j]);
}

// ---------------------------------------------------------------------------
// Kernel 1: projection GEMM (fp16 mma, B packed from fp32 in regs)
//           + bias + fused 2x2 maxpool; fp16 outputs.   (R16 version)
// ---------------------------------------------------------------------------
__global__ __launch_bounds__(256)
void proj_gemm(const float* __restrict__ x,
               const float* __restrict__ bf, const float* __restrict__ bg,
               const float* __restrict__ bh)
{
    extern __shared__ uint32_t smp[];
    uint32_t* As = smp;                       // 2 x [64 m][AP20] fp16
    uint32_t* Bs = As + 2 * 64 * AP20;        // 2 x [32 k][PB] fp32

    const int b  = blockIdx.z;
    const int n0 = blockIdx.x * 128;
    const int m0 = blockIdx.y * 64;
    const float* xb = x + (size_t)b * C_IN * HW;

    const int t = threadIdx.x, lane = t & 31, wid = t >> 5;
    const int wm = wid & 1, wn = wid >> 1;

    auto issue_chunk = [&](int k0, int buf) {
        uint32_t* ad = As + buf * 64 * AP20;
        uint32_t* bd = Bs + buf * 32 * PB;
        {
            int m = t >> 2, seg = t & 3;
            cp16(&ad[m * AP20 + seg * 4], d_wcat16 + (size_t)(m0 + m) * C_IN + k0 + seg * 8);
        }
        #pragma unroll
        for (int ii = 0; ii < 4; ii++) {
            int i = t + ii * 256;
            int k = i >> 5, n4 = (i & 31) * 4;
            cp16(&bd[k * PB + n4], xb + (size_t)(k0 + k) * HW + n0 + n4);
        }
        cp_commit();
    };

    issue_chunk(0, 0);

    float acc[2][4][4] = {};

    for (int ic = 0; ic < 8; ic++) {
        cp_wait_all();
        __syncthreads();
        if (ic + 1 < 8) issue_chunk((ic + 1) * 32, (ic + 1) & 1);

        const uint32_t* abuf = As + (ic & 1) * 64 * AP20;
        const float* bbuf = reinterpret_cast<const float*>(Bs + (ic & 1) * 32 * PB);

        #pragma unroll
        for (int kk = 0; kk < 2; kk++) {
            uint32_t a0[4], a1[4];
            ldsmA(a0, abuf, AP20, wm * 32,      kk * 8, lane);
            ldsmA(a1, abuf, AP20, wm * 32 + 16, kk * 8, lane);
            int kb = kk * 16 + 2 * (lane & 3);
            int nb = wn * 32 + (lane >> 2);
            uint32_t bfr[4][2];
            #pragma unroll
            for (int ntp = 0; ntp < 4; ntp++) {
                int n = nb + ntp * 8;
                bfr[ntp][0] = h2pack(bbuf[(size_t)kb * PB + n],       bbuf[(size_t)(kb + 1) * PB + n]);
                bfr[ntp][1] = h2pack(bbuf[(size_t)(kb + 8) * PB + n], bbuf[(size_t)(kb + 9) * PB + n]);
            }
            mma16h(acc[0][0], a0, bfr[0]); mma16h(acc[0][1], a0, bfr[1]);
            mma16h(acc[0][2], a0, bfr[2]); mma16h(acc[0][3], a0, bfr[3]);
            mma16h(acc[1][0], a1, bfr[0]); mma16h(acc[1][1], a1, bfr[1]);
            mma16h(acc[1][2], a1, bfr[2]); mma16h(acc[1][3], a1, bfr[3]);
        }
    }
    __syncthreads();

    __half* fsm = reinterpret_cast<__half*>(As);                  // [128 q][32 c]
    float* psm  = reinterpret_cast<float*>(Bs);                   // [64][2][32]

    #pragma unroll
    for (int mt = 0; mt < 2; mt++) {
        #pragma unroll
        for (int dr = 0; dr < 2; dr++) {
            int ocl = wm * 32 + mt * 16 + dr * 8 + (lane >> 2);
            int oc = m0 + ocl;
            #pragma unroll
            for (int nt = 0; nt < 4; nt++) {
                int nloc = wn * 32 + nt * 8 + 2 * (lane & 3);
                float v0 = acc[mt][nt][dr * 2 + 0];
                float v1 = acc[mt][nt][dr * 2 + 1];
                if (oc < 32) {
                    float bias = bf[oc] * LOG2E;
                    fsm[(size_t)nloc * 32 + ocl]       = __float2half(v0 + bias);
                    fsm[(size_t)(nloc + 1) * 32 + ocl] = __float2half(v1 + bias);
                } else {
                    int pr = nloc >> 6;
                    int pw = (nloc & 63) >> 1;
                    psm[ocl * 64 + pr * 32 + pw] = fmaxf(v0, v1);
                }
            }
        }
    }
    __syncthreads();

    int ph = n0 >> 7;
    for (int i = t; i < 64 * 32; i += 256) {
        int ocl = i >> 5, pw = i & 31;
        int oc = m0 + ocl;
        if (oc >= 32) {
            float v = fmaxf(psm[ocl * 64 + pw], psm[ocl * 64 + 32 + pw]);
            int l = ph * 32 + pw;
            if (oc < 64)
                d_g16[((size_t)b * HWP + l) * CK + (oc - 32)] = __float2half(v + bg[oc - 32]);
            else
                d_h16[((size_t)b * CH + (oc - 64)) * HWP + l] = __float2half(v + bh[oc - 64]);
        }
    }
    if (m0 == 0) {
        #pragma unroll
        for (int ii = 0; ii < 2; ii++) {
            int i = t + ii * 256;
            int q = i >> 2, seg = i & 3;
            *reinterpret_cast<uint4*>(d_f16 + ((size_t)b * HW + n0 + q) * CK + seg * 8) =
                *reinterpret_cast<const uint4*>(fsm + (size_t)q * 32 + seg * 8);
        }
    }
}

// ---------------------------------------------------------------------------
// Kernel 2: fp16 flash attention (R15 structure: LC=64) + f16x2 exp fusion
//           + fused output conv + residual.
// ---------------------------------------------------------------------------
__global__ __launch_bounds__(256, 2)
void attn_kernel(const float* __restrict__ x,
                 const float* __restrict__ bv,
                 const float* __restrict__ gamma_p,
                 float* __restrict__ out)
{
    extern __shared__ uint32_t sm[];
    uint32_t* g_s = sm;                          // 2 x [64 l][GP20]    2560 w
    uint32_t* h_s = g_s + 2 * 64 * GP20;         // 2 x [128 c][HS36]   9216 w
    uint32_t* p_u = h_s + 2 * 128 * HS36;        // [64 q][PP36] fp16   2304 w
    float* maxp     = reinterpret_cast<float*>(p_u + 64 * PP36);   // [4][64]
    float* row_part = maxp + 256;                                  // [4][64]
    // epilogue overlays (13056 w <= 14080 w of g+h+p):
    uint32_t* o_s  = sm;                         // [64 q][OP68]
    uint32_t* wv_s = sm + 64 * OP68;             // 2 x [64 oc][OP68]

    const int b  = blockIdx.y;
    const int q0 = blockIdx.x * 64;
    const int t = threadIdx.x, lane = t & 31, wid = t >> 5;
    const int wm = wid & 1, wn = wid >> 1;

    const __half* fb = d_f16 + (size_t)b * HW * CK;
    const __half* gb = d_g16 + (size_t)b * HWP * CK;
    const __half* hb = d_h16 + (size_t)b * CH * HWP;

    auto issue_chunk = [&](int lc, int buf) {
        uint32_t* gd = g_s + buf * 64 * GP20;
        uint32_t* hd = h_s + buf * 128 * HS36;
        {
            int l = t & 63, cseg = t >> 6;
            cp16(&gd[l * GP20 + cseg * 4], gb + (size_t)(lc + l) * CK + cseg * 8);
        }
        #pragma unroll
        for (int ii = 0; ii < 4; ii++) {
            int i = t + ii * 256;
            int c = i >> 3, lseg = i & 7;
            cp16(&hd[c * HS36 + lseg * 4], hb + (size_t)c * HWP + lc + lseg * 8);
        }
        cp_commit();
    };

    issue_chunk(0, 0);

    // f A-fragments (fp16 m16k16), constant across chunks
    uint32_t fa[2][2][4];
    {
        int r0 = q0 + wm * 32 + (lane >> 2);
        int c0 = 2 * (lane & 3);
        #pragma unroll
        for (int mt = 0; mt < 2; mt++)
            #pragma unroll
            for (int kk = 0; kk < 2; kk++)
                #pragma unroll
                for (int j = 0; j < 4; j++) {
                    int row = r0 + mt * 16 + 8 * (j & 1);
                    int col = kk * 16 + 8 * (j >> 1) + c0;
                    fa[mt][kk][j] = *reinterpret_cast<const uint32_t*>(fb + (size_t)row * CK + col);
                }
    }

    float acc[2][4][4] = {};
    float rsum[2][2] = {};
    float mrun[2][2] = {{-1e30f, -1e30f}, {-1e30f, -1e30f}};

    for (int ic = 0; ic < NCHUNK; ic++) {
        cp_wait_all();
        __syncthreads();
        if (ic + 1 < NCHUNK) issue_chunk((ic + 1) * LC, (ic + 1) & 1);

        const uint32_t* gbuf = g_s + (ic & 1) * 64 * GP20;
        const uint32_t* hbuf = h_s + (ic & 1) * 128 * HS36;

        // --- S' = (f*log2e) * g  (warp: 32q x 16l) ---
        float sacc[2][2][4] = {};
        #pragma unroll
        for (int kk = 0; kk < 2; kk++) {
            uint32_t bq[4];
            ldsmB(bq, gbuf, GP20, wn * 16, kk * 8, lane);
            mma16h(sacc[0][0], fa[0][kk], bq); mma16h(sacc[0][1], fa[0][kk], bq + 2);
            mma16h(sacc[1][0], fa[1][kk], bq); mma16h(sacc[1][1], fa[1][kk], bq + 2);
        }

        // --- per-chunk row max (exact) ---
        float lmax[2][2];
        #pragma unroll
        for (int mt = 0; mt < 2; mt++) {
            lmax[mt][0] = fmaxf(fmaxf(sacc[mt][0][0], sacc[mt][0][1]),
                                fmaxf(sacc[mt][1][0], sacc[mt][1][1]));
            lmax[mt][1] = fmaxf(fmaxf(sacc[mt][0][2], sacc[mt][0][3]),
                                fmaxf(sacc[mt][1][2], sacc[mt][1][3]));
            #pragma unroll
            for (int hh = 0; hh < 2; hh++) {
                float v = lmax[mt][hh];
                v = fmaxf(v, __shfl_xor_sync(0xffffffffu, v, 1));
                v = fmaxf(v, __shfl_xor_sync(0xffffffffu, v, 2));
                lmax[mt][hh] = v;
            }
        }
        if ((lane & 3) == 0) {
            #pragma unroll
            for (int mt = 0; mt < 2; mt++) {
                int rb = wm * 32 + mt * 16 + (lane >> 2);
                maxp[wn * 64 + rb]     = lmax[mt][0];
                maxp[wn * 64 + rb + 8] = lmax[mt][1];
            }
        }
        __syncthreads();

        // --- rescale, exp2 (f16x2 fused), store P (fp16) ---
        #pragma unroll
        for (int mt = 0; mt < 2; mt++) {
            int rb = wm * 32 + mt * 16 + (lane >> 2);
            float cm0 = fmaxf(fmaxf(maxp[rb],       maxp[64 + rb]),
                              fmaxf(maxp[128 + rb], maxp[192 + rb]));
            float cm1 = fmaxf(fmaxf(maxp[rb + 8],       maxp[64 + rb + 8]),
                              fmaxf(maxp[128 + rb + 8], maxp[192 + rb + 8]));
            float mn0 = fmaxf(mrun[mt][0], cm0);
            float mn1 = fmaxf(mrun[mt][1], cm1);
            float corr0 = ex2f(mrun[mt][0] - mn0);
            float corr1 = ex2f(mrun[mt][1] - mn1);
            mrun[mt][0] = mn0; mrun[mt][1] = mn1;
            float ls0 = 0.f, ls1 = 0.f;
            #pragma unroll
            for (int nt = 0; nt < 2; nt++) {
                int cl = wn * 16 + nt * 8 + 2 * (lane & 3);
                uint32_t p01 = ex2h2(h2pack(sacc[mt][nt][0] - mn0, sacc[mt][nt][1] - mn0));
                uint32_t p23 = ex2h2(h2pack(sacc[mt][nt][2] - mn1, sacc[mt][nt][3] - mn1));
                p_u[rb * PP36 + (cl >> 1)]       = p01;
                p_u[(rb + 8) * PP36 + (cl >> 1)] = p23;
                float2 f01 = __half22float2(*reinterpret_cast<__half2*>(&p01));
                float2 f23 = __half22float2(*reinterpret_cast<__half2*>(&p23));
                ls0 += f01.x + f01.y;
                ls1 += f23.x + f23.y;
            }
            rsum[mt][0] = rsum[mt][0] * corr0 + ls0;
            rsum[mt][1] = rsum[mt][1] * corr1 + ls1;
            #pragma unroll
            for (int nt = 0; nt < 4; nt++) {
                acc[mt][nt][0] *= corr0; acc[mt][nt][1] *= corr0;
                acc[mt][nt][2] *= corr1; acc[mt][nt][3] *= corr1;
            }
        }
        __syncthreads();

        // --- O += P * h^T  (k=64 l -> 4 k16 steps) ---
        #pragma unroll
        for (int kk = 0; kk < 4; kk++) {
            uint32_t a0[4], a1[4], b01[4], b23[4];
            ldsmA(a0, p_u, PP36, wm * 32,      kk * 8, lane);
            ldsmA(a1, p_u, PP36, wm * 32 + 16, kk * 8, lane);
            ldsmB(b01, hbuf, HS36, wn * 32,      kk * 8, lane);
            ldsmB(b23, hbuf, HS36, wn * 32 + 16, kk * 8, lane);
            mma16h(acc[0][0], a0, b01); mma16h(acc[0][1], a0, b01 + 2);
            mma16h(acc[0][2], a0, b23); mma16h(acc[0][3], a0, b23 + 2);
            mma16h(acc[1][0], a1, b01); mma16h(acc[1][1], a1, b01 + 2);
            mma16h(acc[1][2], a1, b23); mma16h(acc[1][3], a1, b23 + 2);
        }
    }

    // final row-sum reduction
    #pragma unroll
    for (int mt = 0; mt < 2; mt++)
        #pragma unroll
        for (int hh = 0; hh < 2; hh++) {
            float s = rsum[mt][hh];
            s += __shfl_xor_sync(0xffffffffu, s, 1);
            s += __shfl_xor_sync(0xffffffffu, s, 2);
            rsum[mt][hh] = s;
        }
    if ((lane & 3) == 0) {
        #pragma unroll
        for (int mt = 0; mt < 2; mt++)
            #pragma unroll
            for (int hh = 0; hh < 2; hh++) {
                int rb = wm * 32 + mt * 16 + hh * 8 + (lane >> 2);
                row_part[wn * 64 + rb] = rsum[mt][hh];
            }
    }
    __syncthreads();

    auto issue_wv = [&](int mc, int buf) {
        uint32_t* ad = wv_s + buf * 64 * OP68;
        #pragma unroll
        for (int ii = 0; ii < 4; ii++) {
            int i = t + ii * 256;
            int m = i >> 4, cseg = i & 15;
            cp16(&ad[m * OP68 + cseg * 4], d_wvt16 + (size_t)(mc * 64 + m) * CH + cseg * 8);
        }
        cp_commit();
    };

    issue_wv(0, 0);

    // normalize O -> o_s [q][c] fp16
    #pragma unroll
    for (int mt = 0; mt < 2; mt++) {
        int rb = wm * 32 + mt * 16 + (lane >> 2);
        float d0 = row_part[rb]     + row_part[64 + rb]     + row_part[128 + rb]     + row_part[192 + rb];
        float d1 = row_part[rb + 8] + row_part[64 + rb + 8] + row_part[128 + rb + 8] + row_part[192 + rb + 8];
        float inv0 = 1.f / d0;
        float inv1 = 1.f / d1;
        #pragma unroll
        for (int nt = 0; nt < 4; nt++) {
            int cc = wn * 32 + nt * 8 + 2 * (lane & 3);
            o_s[rb * OP68 + (cc >> 1)] =
                h2pack(acc[mt][nt][0] * inv0, acc[mt][nt][1] * inv0);
            o_s[(rb + 8) * OP68 + (cc >> 1)] =
                h2pack(acc[mt][nt][2] * inv1, acc[mt][nt][3] * inv1);
        }
    }

    // out[oc, q] = gamma * (wv @ O^T + bv) + x, 4 oc-chunks of 64 (fp16 mma)
    const float gamma = *gamma_p;

    for (int mc = 0; mc < 4; mc++) {
        cp_wait_all();
        __syncthreads();
        if (mc + 1 < 4) issue_wv(mc + 1, (mc + 1) & 1);

        const uint32_t* abuf = wv_s + (mc & 1) * 64 * OP68;

        float oa[2][2][4] = {};
        #pragma unroll
        for (int kk = 0; kk < 8; kk++) {
            uint32_t a0[4], a1[4], bq[4];
            ldsmA(a0, abuf, OP68, wm * 32,      kk * 8, lane);
            ldsmA(a1, abuf, OP68, wm * 32 + 16, kk * 8, lane);
            ldsmB(bq, o_s, OP68, wn * 16, kk * 8, lane);
            mma16h(oa[0][0], a0, bq); mma16h(oa[0][1], a0, bq + 2);
            mma16h(oa[1][0], a1, bq); mma16h(oa[1][1], a1, bq + 2);
        }

        #pragma unroll
        for (int mt = 0; mt < 2; mt++) {
            #pragma unroll
            for (int dr = 0; dr < 2; dr++) {
                int oc = mc * 64 + wm * 32 + mt * 16 + dr * 8 + (lane >> 2);
                float bias = bv[oc];
                size_t rowoff = ((size_t)b * C_IN + oc) * HW + q0;
                #pragma unroll
                for (int nt = 0; nt < 2; nt++) {
                    int ql = wn * 16 + nt * 8 + 2 * (lane & 3);
                    float2 xv = *reinterpret_cast<const float2*>(x + rowoff + ql);
                    float2 v;
                    v.x = gamma * (oa[mt][nt][dr * 2 + 0] + bias) + xv.x;
                    v.y = gamma * (oa[mt][nt][dr * 2 + 1] + bias) + xv.y;
                    *reinterpret_cast<float2*>(out + rowoff + ql) = v;
                }
            }
        }
    }
}

// ---------------------------------------------------------------------------
extern "C" void kernel_launch(void* const* d_in, const int* in_sizes, int n_in,
                              void* d_out, int out_size)
{
    const float* x  = (const float*)d_in[0];
    const float* wf = (const float*)d_in[1];
    const float* bf = (const float*)d_in[2];
    const float* wg = (const float*)d_in[3];
    const float* bg = (const float*)d_in[4];
    const float* wh = (const float*)d_in[5];
    const float* bh = (const float*)d_in[6];
    const float* wv = (const float*)d_in[7];
    const float* bv = (const float*)d_in[8];
    const float* gamma = (const float*)d_in[9];
    float* out = (float*)d_out;

    const int proj_smem = (2 * 64 * AP20 + 2 * 32 * PB) * (int)sizeof(uint32_t);
    const int attn_smem =
        (2 * 64 * GP20 + 2 * 128 * HS36 + 64 * PP36 + 512) * (int)sizeof(uint32_t);

    cudaFuncSetAttribute(proj_gemm,   cudaFuncAttributeMaxDynamicSharedMemorySize, proj_smem);
    cudaFuncSetAttribute(attn_kernel, cudaFuncAttributeMaxDynamicSharedMemorySize, attn_smem);

    int prep_total = OC_TOT * C_IN + C_IN * CH;
    prep_weights<<<(prep_total + 255) / 256, 256>>>(wf, wg, wh, wv);

    dim3 g1(HW / 128, OC_TOT / 64, BATCH);
    proj_gemm<<<g1, 256, proj_smem>>>(x, bf, bg, bh);

    dim3 g3(HW / 64, BATCH);
    attn_kernel<<<g3, 256, attn_smem>>>(x, bv, gamma, out);
}